// round 6
// baseline (speedup 1.0000x reference)
#include <cuda_runtime.h>
#include <cstdint>

#define B 32
#define D 128
#define DIN 2048
#define A 7
#define K 5
#define TR 128           // reps rows per tile
#define GBLK 148         // 1 CTA per SM, exactly one wave (required for last-block finalize)
#define PITCH 33         // ulonglong2 (16B) units per tile row = 132 floats (odd -> conflict-free)
#define KSPLIT 16
#define KSLICE (DIN / KSPLIT)   // 128

typedef unsigned long long ull;

// ---------------- scratch (no allocations allowed) ----------------
__device__ float g_partial[KSPLIT * B * D];
__device__ float g_brep[B * D];
__device__ float g_anorm[B];
__device__ float g_cand_d[B * GBLK * K];   // [batch][block][5]
__device__ int   g_cand_i[B * GBLK * K];
__device__ unsigned g_done;                // zero-init; reset by finalizer every launch

// ---------------- f32x2 helpers (packed double-rate fp32) ----------------
__device__ __forceinline__ void ffma2(ull& d, const ull a, const ull b) {
    asm("fma.rn.f32x2 %0, %1, %2, %0;" : "+l"(d) : "l"(a), "l"(b));
}
__device__ __forceinline__ float2 unpack2(ull v) {
    float2 r;
    asm("mov.b64 {%0, %1}, %2;" : "=f"(r.x), "=f"(r.y) : "l"(v));
    return r;
}

// ---------------- NaN-safe top-5 insert on register arrays (ascending) ----------------
__device__ __forceinline__ void ins5(float sq, int idx, float* d, int* ix)
{
    if (!(sq < d[4])) return;
    if (sq < d[2]) {
        d[4] = d[3]; ix[4] = ix[3]; d[3] = d[2]; ix[3] = ix[2];
        if (sq < d[1]) {
            d[2] = d[1]; ix[2] = ix[1];
            if (sq < d[0]) { d[1] = d[0]; ix[1] = ix[0]; d[0] = sq; ix[0] = idx; }
            else           { d[1] = sq; ix[1] = idx; }
        } else { d[2] = sq; ix[2] = idx; }
    } else {
        if (sq < d[3]) { d[4] = d[3]; ix[4] = ix[3]; d[3] = sq; ix[3] = idx; }
        else           { d[4] = sq; ix[4] = idx; }
    }
}

// ---------------- kernel 1: encoder split-K partial GEMM ----------------
__global__ void enc_partial_kernel(const float* __restrict__ x,
                                   const float* __restrict__ W)
{
    const int ks = blockIdx.x;
    const int b  = blockIdx.y;
    const int d  = threadIdx.x;
    __shared__ float xs[KSLICE];
    xs[d] = x[b * DIN + ks * KSLICE + d];
    __syncthreads();
    const float* Wp = W + (size_t)(ks * KSLICE) * D + d;
    float acc = 0.f;
#pragma unroll 8
    for (int i = 0; i < KSLICE; i++)
        acc = fmaf(xs[i], Wp[(size_t)i * D], acc);
    g_partial[(ks * B + b) * D + d] = acc;
}

// ---------------- kernel 1b: reduce partials, add bias, |a|^2 ----------------
__global__ void enc_reduce_kernel(const float* __restrict__ b_enc)
{
    const int b = blockIdx.x;
    const int d = threadIdx.x;
    float r = b_enc[d];
#pragma unroll
    for (int ks = 0; ks < KSPLIT; ks++)
        r += g_partial[(ks * B + b) * D + d];
    g_brep[b * D + d] = r;

    float s = r * r;
#pragma unroll
    for (int o = 16; o; o >>= 1) s += __shfl_xor_sync(0xffffffffu, s, o);
    __shared__ float ws[4];
    if ((d & 31) == 0) ws[d >> 5] = s;
    __syncthreads();
    if (d == 0) g_anorm[b] = ws[0] + ws[1] + ws[2] + ws[3];
}

// ---------------- cp.async tile load: 256 threads, 128 rows x 128 floats ----------------
__device__ __forceinline__ void load_tile_async(ulonglong2* buf,
                                                const float* __restrict__ reps,
                                                int row0, int N, int tid)
{
#pragma unroll
    for (int j = 0; j < 16; j++) {
        const int c   = tid + j * 256;     // 0..4095
        const int row = c >> 5;
        const int col = c & 31;            // 16B column
        const int gr  = row0 + row;
        if (gr < N) {
            const float4* src = (const float4*)reps + (size_t)gr * 32 + col;
            unsigned dst = (unsigned)__cvta_generic_to_shared(buf + row * PITCH + col);
            asm volatile("cp.async.cg.shared.global [%0], [%1], 16;"
                         :: "r"(dst), "l"(src) : "memory");
        }
    }
}

// ---------------- kernel 2: fused cdist (outer-product f32x2) + top-5 + finalize ----------------
// 256 threads, 8 warps. Thread (bi = lane&7, rj = lane>>3) owns batches {bi+8bb} x rows {w*16+rj+4rr}.
// All fragment LDS.128 are conflict-free (odd pitch + strided ownership).
__global__ void __launch_bounds__(256) dist_topk_kernel(
    const float* __restrict__ reps, int N,
    const float* __restrict__ actions, float* __restrict__ out)
{
    extern __shared__ char smraw[];
    ulonglong2* a_s  = (ulonglong2*)smraw;                 // 32*33 u2  = 16896 B
    ulonglong2* buf0 = a_s + 32 * PITCH;                   // 128*33 u2 = 67584 B
    ulonglong2* buf1 = buf0 + 128 * PITCH;                 // 67584 B
    float* rn0 = (float*)(buf1 + 128 * PITCH);             // 128 floats
    float* rn1 = rn0 + 128;

    const int tid  = threadIdx.x;
    const int lane = tid & 31;
    const int w    = tid >> 5;
    const int bi   = lane & 7;
    const int rj   = lane >> 3;

    // stage batch reps into smem: a_s[batch][c]  (32 u2 per batch + 1 pad)
    for (int i = tid; i < 32 * 32; i += 256) {
        const int b = i >> 5, c = i & 31;
        a_s[b * PITCH + c] = ((const ulonglong2*)g_brep)[b * 32 + c];
    }

    float an[4];
#pragma unroll
    for (int bb = 0; bb < 4; bb++) an[bb] = g_anorm[bi + 8 * bb];

    float td[4][5];
    int   ti[4][5];
#pragma unroll
    for (int bb = 0; bb < 4; bb++)
#pragma unroll
        for (int j = 0; j < 5; j++) { td[bb][j] = 3.4e38f; ti[bb][j] = 0; }

    const int ntiles = (N + TR - 1) / TR;

    // prologue: async-load first tile
    if (blockIdx.x < ntiles)
        load_tile_async(buf0, reps, blockIdx.x * TR, N, tid);
    asm volatile("cp.async.commit_group;" ::: "memory");

    int i = 0;
    for (int t = blockIdx.x; t < ntiles; t += GBLK, ++i) {
        ulonglong2* cur = (i & 1) ? buf1 : buf0;
        ulonglong2* nxt = (i & 1) ? buf0 : buf1;
        float*      rnc = (i & 1) ? rn1  : rn0;

        const int tn = t + GBLK;
        if (tn < ntiles)
            load_tile_async(nxt, reps, tn * TR, N, tid);
        asm volatile("cp.async.commit_group;" ::: "memory");
        asm volatile("cp.async.wait_group 1;" ::: "memory");   // cur ready
        __syncthreads();

        // ---- row-norm pass: 2 threads per row (per-lane-distinct, cheap) ----
        {
            const int row  = tid >> 1;
            const int half = tid & 1;
            const int gr   = t * TR + row;
            const ulonglong2* rp = cur + row * PITCH + half * 16;
            ull nacc = 0;
#pragma unroll
            for (int kk = 0; kk < 16; kk++) {
                ulonglong2 v = rp[kk];
                ffma2(nacc, v.x, v.x);
                ffma2(nacc, v.y, v.y);
            }
            float2 nf = unpack2(nacc);
            float s = nf.x + nf.y;
            s += __shfl_xor_sync(0xffffffffu, s, 1);
            if (half == 0) rnc[row] = (gr < N) ? s : 3.4e38f;
        }
        __syncthreads();

        // ---- compute: 4 batches x 4 rows per thread, packed f32x2 ----
        {
            const ulonglong2* ap = a_s + bi * PITCH;
            const ulonglong2* qp = cur + (w * 16 + rj) * PITCH;
            ull acc[16];
#pragma unroll
            for (int z = 0; z < 16; z++) acc[z] = 0ull;

#pragma unroll 4
            for (int c = 0; c < 32; c++) {
                const ulonglong2 a0 = ap[c];
                const ulonglong2 a1 = ap[8 * PITCH + c];
                const ulonglong2 a2 = ap[16 * PITCH + c];
                const ulonglong2 a3 = ap[24 * PITCH + c];
                const ulonglong2 q0 = qp[c];
                const ulonglong2 q1 = qp[4 * PITCH + c];
                const ulonglong2 q2 = qp[8 * PITCH + c];
                const ulonglong2 q3 = qp[12 * PITCH + c];
                ffma2(acc[ 0], a0.x, q0.x); ffma2(acc[ 0], a0.y, q0.y);
                ffma2(acc[ 1], a0.x, q1.x); ffma2(acc[ 1], a0.y, q1.y);
                ffma2(acc[ 2], a0.x, q2.x); ffma2(acc[ 2], a0.y, q2.y);
                ffma2(acc[ 3], a0.x, q3.x); ffma2(acc[ 3], a0.y, q3.y);
                ffma2(acc[ 4], a1.x, q0.x); ffma2(acc[ 4], a1.y, q0.y);
                ffma2(acc[ 5], a1.x, q1.x); ffma2(acc[ 5], a1.y, q1.y);
                ffma2(acc[ 6], a1.x, q2.x); ffma2(acc[ 6], a1.y, q2.y);
                ffma2(acc[ 7], a1.x, q3.x); ffma2(acc[ 7], a1.y, q3.y);
                ffma2(acc[ 8], a2.x, q0.x); ffma2(acc[ 8], a2.y, q0.y);
                ffma2(acc[ 9], a2.x, q1.x); ffma2(acc[ 9], a2.y, q1.y);
                ffma2(acc[10], a2.x, q2.x); ffma2(acc[10], a2.y, q2.y);
                ffma2(acc[11], a2.x, q3.x); ffma2(acc[11], a2.y, q3.y);
                ffma2(acc[12], a3.x, q0.x); ffma2(acc[12], a3.y, q0.y);
                ffma2(acc[13], a3.x, q1.x); ffma2(acc[13], a3.y, q1.y);
                ffma2(acc[14], a3.x, q2.x); ffma2(acc[14], a3.y, q2.y);
                ffma2(acc[15], a3.x, q3.x); ffma2(acc[15], a3.y, q3.y);
            }

            const int rbase = w * 16 + rj;
            const float r0 = rnc[rbase];
            const float r1 = rnc[rbase + 4];
            const float r2 = rnc[rbase + 8];
            const float r3 = rnc[rbase + 12];
            const int grow = t * TR + rbase;
#pragma unroll
            for (int bb = 0; bb < 4; bb++) {
                float2 f;
                f = unpack2(acc[bb * 4 + 0]);
                ins5(an[bb] + r0 - 2.f * (f.x + f.y), grow,      td[bb], ti[bb]);
                f = unpack2(acc[bb * 4 + 1]);
                ins5(an[bb] + r1 - 2.f * (f.x + f.y), grow + 4,  td[bb], ti[bb]);
                f = unpack2(acc[bb * 4 + 2]);
                ins5(an[bb] + r2 - 2.f * (f.x + f.y), grow + 8,  td[bb], ti[bb]);
                f = unpack2(acc[bb * 4 + 3]);
                ins5(an[bb] + r3 - 2.f * (f.x + f.y), grow + 12, td[bb], ti[bb]);
            }
        }
        __syncthreads();   // tile consumed; buffer may be refilled next iter
    }

    // ---- block merge: 256 threads x 4 lists -> 5 per batch ----
    float* md = (float*)buf0;                     // [256][4][5] floats = 20KB
    int*   mi = (int*)(md + 256 * 4 * 5);         // 20KB
#pragma unroll
    for (int bb = 0; bb < 4; bb++)
#pragma unroll
        for (int j = 0; j < 5; j++) {
            md[(tid * 4 + bb) * 5 + j] = td[bb][j];
            mi[(tid * 4 + bb) * 5 + j] = ti[bb][j];
        }
    __syncthreads();
    if (tid < 32) {
        const int b = tid, sbi = b & 7, sbb = b >> 3;
        float e[5]; int m[5];
#pragma unroll
        for (int j = 0; j < 5; j++) { e[j] = 3.4e38f; m[j] = 0; }
        for (int ww = 0; ww < 8; ww++)
            for (int srj = 0; srj < 4; srj++) {
                const int src = ((ww * 32 + srj * 8 + sbi) * 4 + sbb) * 5;
#pragma unroll
                for (int j = 0; j < 5; j++) ins5(md[src + j], mi[src + j], e, m);
            }
        const int ob = (b * GBLK + blockIdx.x) * K;
#pragma unroll
        for (int j = 0; j < 5; j++) { g_cand_d[ob + j] = e[j]; g_cand_i[ob + j] = m[j]; }
    }

    // ---- last-block finalize (all 148 CTAs are co-resident: one wave) ----
    __threadfence();
    __syncthreads();
    __shared__ unsigned rank_s;
    if (tid == 0) rank_s = atomicAdd(&g_done, 1u);
    __syncthreads();
    if (rank_s != GBLK - 1) return;

    {
        const int b = tid >> 3, s = tid & 7;      // 8 threads per batch
        float e[5]; int m[5];
#pragma unroll
        for (int j = 0; j < 5; j++) { e[j] = 3.4e38f; m[j] = 0; }
        const float* cd = g_cand_d + (size_t)b * GBLK * K;
        const int*   ci = g_cand_i + (size_t)b * GBLK * K;
        for (int c = s; c < GBLK * K; c += 8) ins5(cd[c], ci[c], e, m);

#pragma unroll
        for (int j = 0; j < 5; j++) { md[tid * 5 + j] = e[j]; mi[tid * 5 + j] = m[j]; }
    }
    __syncthreads();
    if (tid < 32) {
        const int b = tid;
        float e[5]; int m[5];
#pragma unroll
        for (int j = 0; j < 5; j++) { e[j] = 3.4e38f; m[j] = 0; }
        for (int s = 0; s < 8; s++) {
            const int src = (b * 8 + s) * 5;
#pragma unroll
            for (int j = 0; j < 5; j++) ins5(md[src + j], mi[src + j], e, m);
        }
        const float t0 = sqrtf(fmaxf(e[0], 1e-12f));
        const float t1 = sqrtf(fmaxf(e[1], 1e-12f));
        const float t2 = sqrtf(fmaxf(e[2], 1e-12f));
        const float t3 = sqrtf(fmaxf(e[3], 1e-12f));
        const float t4 = sqrtf(fmaxf(e[4], 1e-12f));
        const float dmin = t0;   // ascending, sqrt monotone
        const float w0 = expf(dmin - t0);
        const float w1 = expf(dmin - t1);
        const float w2 = expf(dmin - t2);
        const float w3 = expf(dmin - t3);
        const float w4 = expf(dmin - t4);
        const float inv = 1.f / (w0 + w1 + w2 + w3 + w4);
        const float* a0 = actions + (size_t)m[0] * A;
        const float* a1 = actions + (size_t)m[1] * A;
        const float* a2 = actions + (size_t)m[2] * A;
        const float* a3 = actions + (size_t)m[3] * A;
        const float* a4 = actions + (size_t)m[4] * A;
#pragma unroll
        for (int a = 0; a < A; a++)
            out[b * A + a] = (w0 * a0[a] + w1 * a1[a] + w2 * a2[a] +
                              w3 * a3[a] + w4 * a4[a]) * inv;
    }
    if (tid == 0) g_done = 0;   // restore invariant for next launch
}

// ---------------- launch ----------------
extern "C" void kernel_launch(void* const* d_in, const int* in_sizes, int n_in,
                              void* d_out, int out_size)
{
    const float* x       = (const float*)d_in[0];
    const float* W       = (const float*)d_in[1];
    const float* b_enc   = (const float*)d_in[2];
    const float* reps    = (const float*)d_in[3];
    const float* actions = (const float*)d_in[4];
    const int N = in_sizes[3] / D;

    constexpr int SMEM2 = (32 * PITCH + 2 * 128 * PITCH) * 16 + 2 * 128 * 4;  // 153088 B
    static int attr_done = 0;
    if (!attr_done) {
        cudaFuncSetAttribute(dist_topk_kernel,
                             cudaFuncAttributeMaxDynamicSharedMemorySize, SMEM2);
        attr_done = 1;
    }

    enc_partial_kernel<<<dim3(KSPLIT, B), 128>>>(x, W);
    enc_reduce_kernel<<<B, 128>>>(b_enc);
    dist_topk_kernel<<<GBLK, 256, SMEM2>>>(reps, N, actions, (float*)d_out);
}

// round 8
// speedup vs baseline: 1.3203x; 1.3203x over previous
#include <cuda_runtime.h>
#include <cstdint>

#define B 32
#define D 128
#define DIN 2048
#define A 7
#define K 5
#define TR 128           // reps rows per tile (= GEMM M)
#define GBLK 148         // 1 CTA/SM, one wave (required for last-block finalize)
#define PITCH 33         // staging: ulonglong2 (16B) per row = 132 floats
#define APITCH 272       // bf16 A tile row pitch in bytes (136 bf16) -> conflict-free LDS.32
#define KSPLIT 64
#define KSLICE (DIN / KSPLIT)   // 32
#define BT 8             // batches per enc block

typedef unsigned long long ull;

// ---------------- smem layout (bytes) ----------------
#define OFF_AN   0              // 32 floats
#define OFF_RN   128            // 128 floats
#define OFF_FB   1024           // B fragment buffer: 2 ver x 8 ks x 4 nf x 32 lane x 8B = 16384
#define OFF_AHI  17408          // 128 x APITCH = 34816
#define OFF_ALO  52224          // 34816
#define OFF_STG0 87040          // fp32 staging tile, 128 x 33 u2 = 67584
#define OFF_STG1 154624        // 67584
#define SMEM_TOTAL 222208

// ---------------- scratch ----------------
__device__ float g_partial[KSPLIT * B * D];
__device__ float g_brep[B * D];
__device__ float g_anorm[B];
__device__ float g_cand_d[B * GBLK * K];   // [batch][block][5]
__device__ int   g_cand_i[B * GBLK * K];
__device__ unsigned g_done;

// ---------------- helpers ----------------
// pack bf16(lo of pair)=x, bf16(hi of pair)=y from fp32 bit patterns (truncation split)
__device__ __forceinline__ unsigned pack_hi_trunc(unsigned ux, unsigned uy) {
    return __byte_perm(ux, uy, 0x7632);    // {hi16(ux), hi16(uy)} -> low, high halves
}
__device__ __forceinline__ unsigned pack_bf16x2_rn(float lo_elem, float hi_elem) {
    unsigned r;
    asm("cvt.rn.bf16x2.f32 %0, %1, %2;" : "=r"(r) : "f"(hi_elem), "f"(lo_elem));
    return r;
}
__device__ __forceinline__ float trunc_bf(float v) {
    return __uint_as_float(__float_as_uint(v) & 0xFFFF0000u);
}

__device__ __forceinline__ void mma_bf16(float* c, unsigned a0, unsigned a1,
                                         unsigned a2, unsigned a3,
                                         unsigned b0, unsigned b1) {
    asm volatile(
        "mma.sync.aligned.m16n8k16.row.col.f32.bf16.bf16.f32 "
        "{%0,%1,%2,%3}, {%4,%5,%6,%7}, {%8,%9}, {%0,%1,%2,%3};"
        : "+f"(c[0]), "+f"(c[1]), "+f"(c[2]), "+f"(c[3])
        : "r"(a0), "r"(a1), "r"(a2), "r"(a3), "r"(b0), "r"(b1));
}

// NaN-safe top-5 insert (ascending)
__device__ __forceinline__ void ins5(float sq, int idx, float* d, int* ix)
{
    if (!(sq < d[4])) return;
    if (sq < d[2]) {
        d[4] = d[3]; ix[4] = ix[3]; d[3] = d[2]; ix[3] = ix[2];
        if (sq < d[1]) {
            d[2] = d[1]; ix[2] = ix[1];
            if (sq < d[0]) { d[1] = d[0]; ix[1] = ix[0]; d[0] = sq; ix[0] = idx; }
            else           { d[1] = sq; ix[1] = idx; }
        } else { d[2] = sq; ix[2] = idx; }
    } else {
        if (sq < d[3]) { d[4] = d[3]; ix[4] = ix[3]; d[3] = sq; ix[3] = idx; }
        else           { d[4] = sq; ix[4] = idx; }
    }
}

// ---------------- kernel 1: encoder split-K GEMM (8-batch tile) ----------------
__global__ void enc_partial_kernel(const float* __restrict__ x,
                                   const float* __restrict__ W)
{
    const int ks = blockIdx.x;         // 0..KSPLIT-1
    const int bt = blockIdx.y;         // 0..3
    const int d  = threadIdx.x;        // 0..127
    __shared__ float xs[BT][KSLICE];
    for (int i = d; i < BT * KSLICE; i += 128) {
        const int j = i >> 5, kk = i & 31;
        xs[j][kk] = x[(bt * BT + j) * DIN + ks * KSLICE + kk];
    }
    __syncthreads();
    const float* Wp = W + (size_t)(ks * KSLICE) * D + d;
    float acc[BT];
#pragma unroll
    for (int j = 0; j < BT; j++) acc[j] = 0.f;
#pragma unroll
    for (int i = 0; i < KSLICE; i++) {
        const float wv = Wp[(size_t)i * D];
#pragma unroll
        for (int j = 0; j < BT; j++) acc[j] = fmaf(xs[j][i], wv, acc[j]);
    }
#pragma unroll
    for (int j = 0; j < BT; j++)
        g_partial[(ks * B + bt * BT + j) * D + d] = acc[j];
}

// ---------------- kernel 1b: reduce partials, add bias, |a|^2 ----------------
__global__ void enc_reduce_kernel(const float* __restrict__ b_enc)
{
    const int b = blockIdx.x;
    const int d = threadIdx.x;
    float r = b_enc[d];
#pragma unroll
    for (int ks = 0; ks < KSPLIT; ks++)
        r += g_partial[(ks * B + b) * D + d];
    g_brep[b * D + d] = r;

    float s = r * r;
#pragma unroll
    for (int o = 16; o; o >>= 1) s += __shfl_xor_sync(0xffffffffu, s, o);
    __shared__ float ws[4];
    if ((d & 31) == 0) ws[d >> 5] = s;
    __syncthreads();
    if (d == 0) g_anorm[b] = ws[0] + ws[1] + ws[2] + ws[3];
}

// ---------------- cp.async staging tile load (zero-fill OOB rows) ----------------
__device__ __forceinline__ void load_tile_async(char* sm, int stg_off,
                                                const float* __restrict__ reps,
                                                int row0, int N, int tid)
{
    ulonglong2* buf = (ulonglong2*)(sm + stg_off);
#pragma unroll
    for (int j = 0; j < 16; j++) {
        const int c   = tid + j * 256;
        const int row = c >> 5;
        const int col = c & 31;
        const int gr  = row0 + row;
        const int grc = (gr < N) ? gr : (N - 1);
        const int sz  = (gr < N) ? 16 : 0;         // src-size 0 -> zero fill
        const float4* src = (const float4*)reps + (size_t)grc * 32 + col;
        unsigned dst = (unsigned)__cvta_generic_to_shared(buf + row * PITCH + col);
        asm volatile("cp.async.cg.shared.global [%0], [%1], 16, %2;"
                     :: "r"(dst), "l"(src), "r"(sz) : "memory");
    }
}

// ---------------- kernel 2: mma.sync bf16-split cdist + top-5 + finalize ----------------
__global__ void __launch_bounds__(256) dist_topk_kernel(
    const float* __restrict__ reps, int N,
    const float* __restrict__ actions, float* __restrict__ out)
{
    extern __shared__ char sm[];
    float* an_s = (float*)(sm + OFF_AN);
    float* rn_s = (float*)(sm + OFF_RN);
    ull*   fB   = (ull*)(sm + OFF_FB);

    const int tid  = threadIdx.x;
    const int lane = tid & 31;
    const int w    = tid >> 5;
    const int gid  = lane >> 2;        // mma "groupID"
    const int t4   = lane & 3;         // mma "threadID in group"

    if (tid < 32) an_s[tid] = g_anorm[tid];

    // ---- precompute B fragments (batch matrix 32x128) in mma lane order ----
    // entry e: lane_e = e&31, nf = (e>>5)&3, ks = (e>>7)&7, ver = e>>10
    for (int e = tid; e < 2048; e += 256) {
        const int lane_e = e & 31;
        const int nf  = (e >> 5) & 3;
        const int ks  = (e >> 7) & 7;
        const int ver = e >> 10;
        const int n  = nf * 8 + (lane_e >> 2);
        const int k0 = ks * 16 + (lane_e & 3) * 2;
        const float vx = g_brep[n * D + k0];
        const float vy = g_brep[n * D + k0 + 1];
        const float vz = g_brep[n * D + k0 + 8];
        const float vw = g_brep[n * D + k0 + 9];
        unsigned r0, r1;
        if (ver == 0) {
            r0 = pack_hi_trunc(__float_as_uint(vx), __float_as_uint(vy));
            r1 = pack_hi_trunc(__float_as_uint(vz), __float_as_uint(vw));
        } else {
            r0 = pack_bf16x2_rn(vx - trunc_bf(vx), vy - trunc_bf(vy));
            r1 = pack_bf16x2_rn(vz - trunc_bf(vz), vw - trunc_bf(vw));
        }
        fB[e] = (ull)r0 | ((ull)r1 << 32);
    }

    float td[5]; int ti[5];
#pragma unroll
    for (int j = 0; j < 5; j++) { td[j] = 3.4e38f; ti[j] = 0; }

    const int ntiles = (N + TR - 1) / TR;

    if (blockIdx.x < ntiles)
        load_tile_async(sm, OFF_STG0, reps, blockIdx.x * TR, N, tid);
    asm volatile("cp.async.commit_group;" ::: "memory");

    int i = 0;
    for (int t = blockIdx.x; t < ntiles; t += GBLK, ++i) {
        const int cur_off = (i & 1) ? OFF_STG1 : OFF_STG0;
        const int nxt_off = (i & 1) ? OFF_STG0 : OFF_STG1;
        ulonglong2* cur = (ulonglong2*)(sm + cur_off);

        if (t + GBLK < ntiles)
            load_tile_async(sm, nxt_off, reps, (t + GBLK) * TR, N, tid);
        asm volatile("cp.async.commit_group;" ::: "memory");
        asm volatile("cp.async.wait_group 1;" ::: "memory");
        __syncthreads();

        // ---- convert A tile fp32 -> hi/lo bf16 rows (pitch 272B) + fp32 row norms ----
        {
            const int row = tid >> 1, h = tid & 1;   // 2 threads/row, 64 k each
            const ulonglong2* rp = cur + row * PITCH + h * 16;
            char* ahi = sm + OFF_AHI + row * APITCH + h * 128;
            char* alo = sm + OFF_ALO + row * APITCH + h * 128;
            float nsum = 0.f;
#pragma unroll
            for (int j = 0; j < 16; j++) {
                const ulonglong2 u = rp[j];
                const float4 v = *(const float4*)&u;
                nsum += v.x * v.x + v.y * v.y + v.z * v.z + v.w * v.w;
                const unsigned h0 = pack_hi_trunc(__float_as_uint(v.x), __float_as_uint(v.y));
                const unsigned h1 = pack_hi_trunc(__float_as_uint(v.z), __float_as_uint(v.w));
                const unsigned l0 = pack_bf16x2_rn(v.x - trunc_bf(v.x), v.y - trunc_bf(v.y));
                const unsigned l1 = pack_bf16x2_rn(v.z - trunc_bf(v.z), v.w - trunc_bf(v.w));
                *(ull*)(ahi + j * 8) = (ull)h0 | ((ull)h1 << 32);
                *(ull*)(alo + j * 8) = (ull)l0 | ((ull)l1 << 32);
            }
            nsum += __shfl_xor_sync(0xffffffffu, nsum, 1);
            if (h == 0) rn_s[row] = (t * TR + row < N) ? nsum : 3.4e38f;
        }
        __syncthreads();

        // ---- GEMM: 3 passes (hi*hi, hi*lo, lo*hi), per warp m16 x n32 x k128 ----
        float c[4][4];
#pragma unroll
        for (int nf = 0; nf < 4; nf++)
#pragma unroll
            for (int q = 0; q < 4; q++) c[nf][q] = 0.f;

        const int m0 = w * 16 + gid;
#pragma unroll
        for (int pass = 0; pass < 3; pass++) {
            const char* Ab = sm + ((pass == 2) ? OFF_ALO : OFF_AHI)
                           + m0 * APITCH + t4 * 4;
            const ull* fb = fB + (pass == 1 ? 8 * 4 * 32 : 0);
#pragma unroll
            for (int ks = 0; ks < 8; ks++) {
                const unsigned a0 = *(const unsigned*)(Ab + ks * 32);
                const unsigned a1 = *(const unsigned*)(Ab + ks * 32 + 8 * APITCH);
                const unsigned a2 = *(const unsigned*)(Ab + ks * 32 + 16);
                const unsigned a3 = *(const unsigned*)(Ab + ks * 32 + 8 * APITCH + 16);
#pragma unroll
                for (int nf = 0; nf < 4; nf++) {
                    const ull bb = fb[(ks * 4 + nf) * 32 + lane];
                    mma_bf16(c[nf], a0, a1, a2, a3,
                             (unsigned)bb, (unsigned)(bb >> 32));
                }
            }
        }

        // ---- epilogue: sq = an + rn - 2*dot, transpose via smem, scan top-5 ----
        float* sq_s = (float*)cur;                 // staging reusable: [32][129]
        {
            const float rn_a = rn_s[m0];
            const float rn_b = rn_s[m0 + 8];
#pragma unroll
            for (int nf = 0; nf < 4; nf++) {
                const int n0 = nf * 8 + t4 * 2;
                const float an0 = an_s[n0], an1 = an_s[n0 + 1];
                sq_s[n0 * 129 + m0]           = an0 + rn_a - 2.f * c[nf][0];
                sq_s[(n0 + 1) * 129 + m0]     = an1 + rn_a - 2.f * c[nf][1];
                sq_s[n0 * 129 + m0 + 8]       = an0 + rn_b - 2.f * c[nf][2];
                sq_s[(n0 + 1) * 129 + m0 + 8] = an1 + rn_b - 2.f * c[nf][3];
            }
        }
        __syncthreads();
        {
            const float* sp = sq_s + lane * 129 + w * 16;
            const int grow = t * TR + w * 16;
#pragma unroll
            for (int rr = 0; rr < 16; rr++)
                ins5(sp[rr], grow + rr, td, ti);
        }
        __syncthreads();
    }

    // ---- block merge: 8 group-lists per batch -> 5 ----
    float* md = (float*)(sm + OFF_STG0);
    int*   mi = (int*)(sm + OFF_STG0 + 256 * 5 * 4);
#pragma unroll
    for (int j = 0; j < 5; j++) { md[tid * 5 + j] = td[j]; mi[tid * 5 + j] = ti[j]; }
    __syncthreads();
    if (tid < 32) {
        float e[5]; int m[5];
#pragma unroll
        for (int j = 0; j < 5; j++) { e[j] = 3.4e38f; m[j] = 0; }
        for (int g = 0; g < 8; g++) {
            const int src = (g * 32 + tid) * 5;
#pragma unroll
            for (int j = 0; j < 5; j++) ins5(md[src + j], mi[src + j], e, m);
        }
        const int ob = (tid * GBLK + blockIdx.x) * K;
#pragma unroll
        for (int j = 0; j < 5; j++) { g_cand_d[ob + j] = e[j]; g_cand_i[ob + j] = m[j]; }
    }

    // ---- last-block finalize (148 CTAs co-resident: one wave) ----
    __threadfence();
    __syncthreads();
    __shared__ unsigned rank_s;
    if (tid == 0) rank_s = atomicAdd(&g_done, 1u);
    __syncthreads();
    if (rank_s != GBLK - 1) return;

    {
        const int b = tid >> 3, s = tid & 7;      // 8 threads per batch
        float e[5]; int m[5];
#pragma unroll
        for (int j = 0; j < 5; j++) { e[j] = 3.4e38f; m[j] = 0; }
        const float* cd = g_cand_d + (size_t)b * GBLK * K;
        const int*   ci = g_cand_i + (size_t)b * GBLK * K;
        for (int c2 = s; c2 < GBLK * K; c2 += 8) ins5(cd[c2], ci[c2], e, m);
#pragma unroll
        for (int j = 0; j < 5; j++) { md[tid * 5 + j] = e[j]; mi[tid * 5 + j] = m[j]; }
    }
    __syncthreads();
    if (tid < 32) {
        const int b = tid;
        float e[5]; int m[5];
#pragma unroll
        for (int j = 0; j < 5; j++) { e[j] = 3.4e38f; m[j] = 0; }
        for (int s = 0; s < 8; s++) {
            const int src = (b * 8 + s) * 5;
#pragma unroll
            for (int j = 0; j < 5; j++) ins5(md[src + j], mi[src + j], e, m);
        }
        const float t0 = sqrtf(fmaxf(e[0], 1e-12f));
        const float t1 = sqrtf(fmaxf(e[1], 1e-12f));
        const float t2 = sqrtf(fmaxf(e[2], 1e-12f));
        const float t3 = sqrtf(fmaxf(e[3], 1e-12f));
        const float t4v = sqrtf(fmaxf(e[4], 1e-12f));
        const float dmin = t0;
        const float w0 = expf(dmin - t0);
        const float w1 = expf(dmin - t1);
        const float w2 = expf(dmin - t2);
        const float w3 = expf(dmin - t3);
        const float w4 = expf(dmin - t4v);
        const float inv = 1.f / (w0 + w1 + w2 + w3 + w4);
        const float* a0 = actions + (size_t)m[0] * A;
        const float* a1 = actions + (size_t)m[1] * A;
        const float* a2 = actions + (size_t)m[2] * A;
        const float* a3 = actions + (size_t)m[3] * A;
        const float* a4 = actions + (size_t)m[4] * A;
#pragma unroll
        for (int a = 0; a < A; a++)
            out[b * A + a] = (w0 * a0[a] + w1 * a1[a] + w2 * a2[a] +
                              w3 * a3[a] + w4 * a4[a]) * inv;
    }
    if (tid == 0) g_done = 0;
}

// ---------------- launch ----------------
extern "C" void kernel_launch(void* const* d_in, const int* in_sizes, int n_in,
                              void* d_out, int out_size)
{
    const float* x       = (const float*)d_in[0];
    const float* W       = (const float*)d_in[1];
    const float* b_enc   = (const float*)d_in[2];
    const float* reps    = (const float*)d_in[3];
    const float* actions = (const float*)d_in[4];
    const int N = in_sizes[3] / D;

    static int attr_done = 0;
    if (!attr_done) {
        cudaFuncSetAttribute(dist_topk_kernel,
                             cudaFuncAttributeMaxDynamicSharedMemorySize, SMEM_TOTAL);
        attr_done = 1;
    }

    enc_partial_kernel<<<dim3(KSPLIT, B / BT), 128>>>(x, W);
    enc_reduce_kernel<<<B, 128>>>(b_enc);
    dist_topk_kernel<<<GBLK, 256, SMEM_TOTAL>>>(reps, N, actions, (float*)d_out);
}

// round 11
// speedup vs baseline: 1.5339x; 1.1618x over previous
#include <cuda_runtime.h>
#include <cstdint>

#define B 32
#define D 128
#define DIN 2048
#define A 7
#define K 5
#define TR 128           // reps rows per tile (= GEMM M)
#define GBLK 148         // 1 CTA/SM, one wave (required for last-block finalize)
#define PITCH 33         // staging: ulonglong2 (16B) per row = 132 floats
#define NSTG 3           // pipeline depth
#define KSPLIT 64
#define KSLICE (DIN / KSPLIT)   // 32
#define BT 8             // batches per enc block

typedef unsigned long long ull;

// ---------------- smem layout (bytes) ----------------
#define OFF_AN   0              // 32 floats
#define OFF_RN   128            // 128 floats
#define OFF_SQ   1024           // 32 x 132 floats = 16896
#define OFF_STG  17920          // 3 x (128 x 33 u2 = 67584)
#define STG_SZ   67584
#define SMEM_TOTAL (OFF_STG + NSTG * STG_SZ)   // 220672

// ---------------- scratch ----------------
__device__ float g_partial[KSPLIT * B * D];
__device__ float g_brep[B * D];
__device__ float g_anorm[B];
__device__ float g_cand_d[B * GBLK * K];   // [batch][block][5] (approx sq)
__device__ int   g_cand_i[B * GBLK * K];
__device__ unsigned g_done;

// ---------------- helpers ----------------
__device__ __forceinline__ unsigned cvt_tf32(float v) {
    unsigned r;
    asm("cvt.rna.tf32.f32 %0, %1;" : "=r"(r) : "f"(v));
    return r;
}

__device__ __forceinline__ void mma_tf32(float* c, unsigned a0, unsigned a1,
                                         unsigned a2, unsigned a3,
                                         unsigned b0, unsigned b1) {
    asm volatile(
        "mma.sync.aligned.m16n8k8.row.col.f32.tf32.tf32.f32 "
        "{%0,%1,%2,%3}, {%4,%5,%6,%7}, {%8,%9}, {%0,%1,%2,%3};"
        : "+f"(c[0]), "+f"(c[1]), "+f"(c[2]), "+f"(c[3])
        : "r"(a0), "r"(a1), "r"(a2), "r"(a3), "r"(b0), "r"(b1));
}

// NaN-safe top-5 insert (ascending)
__device__ __forceinline__ void ins5(float sq, int idx, float* d, int* ix)
{
    if (!(sq < d[4])) return;
    if (sq < d[2]) {
        d[4] = d[3]; ix[4] = ix[3]; d[3] = d[2]; ix[3] = ix[2];
        if (sq < d[1]) {
            d[2] = d[1]; ix[2] = ix[1];
            if (sq < d[0]) { d[1] = d[0]; ix[1] = ix[0]; d[0] = sq; ix[0] = idx; }
            else           { d[1] = sq; ix[1] = idx; }
        } else { d[2] = sq; ix[2] = idx; }
    } else {
        if (sq < d[3]) { d[4] = d[3]; ix[4] = ix[3]; d[3] = sq; ix[3] = idx; }
        else           { d[4] = sq; ix[4] = idx; }
    }
}

// NaN-safe top-8 bubble insert (ascending, fully unrolled -> registers)
__device__ __forceinline__ void ins8(float v, int idx, float* d, int* ix)
{
    if (!(v < d[7])) return;
    d[7] = v; ix[7] = idx;
#pragma unroll
    for (int k = 7; k > 0; k--) {
        if (d[k] < d[k - 1]) {
            float tv = d[k]; d[k] = d[k - 1]; d[k - 1] = tv;
            int   tn = ix[k]; ix[k] = ix[k - 1]; ix[k - 1] = tn;
        }
    }
}

// ---------------- kernel 1: encoder split-K GEMM (8-batch tile) ----------------
__global__ void enc_partial_kernel(const float* __restrict__ x,
                                   const float* __restrict__ W)
{
    const int ks = blockIdx.x;
    const int bt = blockIdx.y;
    const int d  = threadIdx.x;
    __shared__ float xs[BT][KSLICE];
    for (int i = d; i < BT * KSLICE; i += 128) {
        const int j = i >> 5, kk = i & 31;
        xs[j][kk] = x[(bt * BT + j) * DIN + ks * KSLICE + kk];
    }
    __syncthreads();
    const float* Wp = W + (size_t)(ks * KSLICE) * D + d;
    float acc[BT];
#pragma unroll
    for (int j = 0; j < BT; j++) acc[j] = 0.f;
#pragma unroll
    for (int i = 0; i < KSLICE; i++) {
        const float wv = Wp[(size_t)i * D];
#pragma unroll
        for (int j = 0; j < BT; j++) acc[j] = fmaf(xs[j][i], wv, acc[j]);
    }
#pragma unroll
    for (int j = 0; j < BT; j++)
        g_partial[(ks * B + bt * BT + j) * D + d] = acc[j];
}

// ---------------- kernel 1b: reduce partials, add bias, |a|^2 ----------------
__global__ void enc_reduce_kernel(const float* __restrict__ b_enc)
{
    const int b = blockIdx.x;
    const int d = threadIdx.x;
    float r = b_enc[d];
#pragma unroll
    for (int ks = 0; ks < KSPLIT; ks++)
        r += g_partial[(ks * B + b) * D + d];
    g_brep[b * D + d] = r;

    float s = r * r;
#pragma unroll
    for (int o = 16; o; o >>= 1) s += __shfl_xor_sync(0xffffffffu, s, o);
    __shared__ float ws[4];
    if ((d & 31) == 0) ws[d >> 5] = s;
    __syncthreads();
    if (d == 0) g_anorm[b] = ws[0] + ws[1] + ws[2] + ws[3];
}

// ---------------- cp.async staging tile load (zero-fill OOB rows) ----------------
__device__ __forceinline__ void load_tile_async(char* sm, int buf,
                                                const float* __restrict__ reps,
                                                int row0, int N, int tid)
{
    ulonglong2* bp = (ulonglong2*)(sm + OFF_STG + buf * STG_SZ);
#pragma unroll
    for (int j = 0; j < 16; j++) {
        const int c   = tid + j * 256;
        const int row = c >> 5;
        const int col = c & 31;
        const int gr  = row0 + row;
        const int grc = (gr < N) ? gr : 0;
        const int sz  = (gr < N) ? 16 : 0;         // src-size 0 -> zero fill
        const float4* src = (const float4*)reps + (size_t)grc * 32 + col;
        unsigned dst = (unsigned)__cvta_generic_to_shared(bp + row * PITCH + col);
        asm volatile("cp.async.cg.shared.global [%0], [%1], 16, %2;"
                     :: "r"(dst), "l"(src), "r"(sz) : "memory");
    }
}

// ---------------- kernel 2: tf32 screening cdist + top-5 + exact refine ----------------
// 256 threads, 8 warps. Warp (wm = w&3, wn = w>>2) owns m-rows [wm*32, wm*32+32) x
// n-cols [wn*16, wn*16+16). B fragments (tile-invariant) live in 64 registers per thread.
__global__ void __launch_bounds__(256) dist_topk_kernel(
    const float* __restrict__ reps, int N,
    const float* __restrict__ actions, float* __restrict__ out)
{
    extern __shared__ char sm[];
    float* an_s = (float*)(sm + OFF_AN);
    float* rn_s = (float*)(sm + OFF_RN);
    float* sq_s = (float*)(sm + OFF_SQ);       // [n=32][m=132]

    const int tid  = threadIdx.x;
    const int lane = tid & 31;
    const int w    = tid >> 5;
    const int gid  = lane >> 2;
    const int t4   = lane & 3;
    const int wm   = w & 3;
    const int wn   = w >> 2;

    if (tid < 32) an_s[tid] = g_anorm[tid];

    // ---- B fragments: tile-invariant, 64 regs (b0,b1 per ks per nf2) ----
    unsigned b0r[16][2], b1r[16][2];
#pragma unroll
    for (int ks = 0; ks < 16; ks++)
#pragma unroll
        for (int nf2 = 0; nf2 < 2; nf2++) {
            const int n = wn * 16 + nf2 * 8 + gid;
            const int k = ks * 8 + t4;
            b0r[ks][nf2] = cvt_tf32(g_brep[n * D + k]);
            b1r[ks][nf2] = cvt_tf32(g_brep[n * D + k + 4]);
        }

    float td[5]; int ti[5];
#pragma unroll
    for (int j = 0; j < 5; j++) { td[j] = 3.4e38f; ti[j] = 0; }

    const int ntiles = (N + TR - 1) / TR;

    // prologue: 2 tiles in flight
    load_tile_async(sm, 0, reps, blockIdx.x * TR, N, tid);
    asm volatile("cp.async.commit_group;" ::: "memory");
    if (blockIdx.x + GBLK < ntiles)
        load_tile_async(sm, 1, reps, (blockIdx.x + GBLK) * TR, N, tid);
    asm volatile("cp.async.commit_group;" ::: "memory");

    int ib = 0;            // current buffer index (0..2)
    int i = 0;
    for (int t = blockIdx.x; t < ntiles; t += GBLK, ++i) {
        const int pb = (ib + 2 >= NSTG) ? ib - 1 : ib + 2;   // (ib+2)%3
        if (t + 2 * GBLK < ntiles)
            load_tile_async(sm, pb, reps, (t + 2 * GBLK) * TR, N, tid);
        asm volatile("cp.async.commit_group;" ::: "memory");
        asm volatile("cp.async.wait_group 2;" ::: "memory");   // current tile ready
        __syncthreads();

        const float* stgf = (const float*)(sm + OFF_STG + ib * STG_SZ);

        // ---- row norms (fp32 exact): 2 threads per row ----
        {
            const int row = tid >> 1, h = tid & 1;
            const float4* rp = (const float4*)stgf + row * PITCH + h * 16;
            float nsum = 0.f;
#pragma unroll
            for (int j = 0; j < 16; j++) {
                const float4 v = rp[j];
                nsum += v.x * v.x + v.y * v.y + v.z * v.z + v.w * v.w;
            }
            nsum += __shfl_xor_sync(0xffffffffu, nsum, 1);
            if (h == 0) rn_s[row] = (t * TR + row < N) ? nsum : 3.4e38f;
        }

        // ---- tf32 GEMM: warp computes m32 x n16 x k128, A straight from staging ----
        float c[2][2][4];
#pragma unroll
        for (int mf = 0; mf < 2; mf++)
#pragma unroll
            for (int nf2 = 0; nf2 < 2; nf2++)
#pragma unroll
                for (int q = 0; q < 4; q++) c[mf][nf2][q] = 0.f;

        const unsigned* ap = (const unsigned*)stgf + (wm * 32 + gid) * 132 + t4;
#pragma unroll
        for (int ks = 0; ks < 16; ks++) {
            const int o = ks * 8;
            const unsigned a00 = ap[o];
            const unsigned a01 = ap[o + 8 * 132];
            const unsigned a02 = ap[o + 4];
            const unsigned a03 = ap[o + 8 * 132 + 4];
            const unsigned a10 = ap[o + 16 * 132];
            const unsigned a11 = ap[o + 24 * 132];
            const unsigned a12 = ap[o + 16 * 132 + 4];
            const unsigned a13 = ap[o + 24 * 132 + 4];
            mma_tf32(c[0][0], a00, a01, a02, a03, b0r[ks][0], b1r[ks][0]);
            mma_tf32(c[0][1], a00, a01, a02, a03, b0r[ks][1], b1r[ks][1]);
            mma_tf32(c[1][0], a10, a11, a12, a13, b0r[ks][0], b1r[ks][0]);
            mma_tf32(c[1][1], a10, a11, a12, a13, b0r[ks][1], b1r[ks][1]);
        }
        __syncthreads();   // rn_s complete for all, GEMM reads of staging done

        // ---- epilogue: sq = an + rn - 2*dot into sq buffer (conflict-free) ----
#pragma unroll
        for (int mf = 0; mf < 2; mf++) {
            const int R = wm * 32 + mf * 16 + gid;
            const float rn0 = rn_s[R], rn1 = rn_s[R + 8];
#pragma unroll
            for (int nf2 = 0; nf2 < 2; nf2++) {
                const int C = wn * 16 + nf2 * 8 + 2 * t4;
                const float an0 = an_s[C], an1 = an_s[C + 1];
                sq_s[C * 132 + R]           = an0 + rn0 - 2.f * c[mf][nf2][0];
                sq_s[(C + 1) * 132 + R]     = an1 + rn0 - 2.f * c[mf][nf2][1];
                sq_s[C * 132 + R + 8]       = an0 + rn1 - 2.f * c[mf][nf2][2];
                sq_s[(C + 1) * 132 + R + 8] = an1 + rn1 - 2.f * c[mf][nf2][3];
            }
        }
        __syncthreads();

        // ---- scan: thread (batch=lane, rowgroup=w) top-5 over 16 rows ----
        {
            const float* sp = sq_s + lane * 132 + w * 16;
            const int grow = t * TR + w * 16;
#pragma unroll
            for (int rr = 0; rr < 16; rr++)
                ins5(sp[rr], grow + rr, td, ti);
        }
        // no sync needed: sq_s rewritten only after next iteration's syncthreads

        ib = (ib + 1 >= NSTG) ? 0 : ib + 1;
    }

    // ---- block merge: 8 group-lists per batch -> 5 (approx) ----
    float* md = (float*)(sm + OFF_STG);
    int*   mi = (int*)(sm + OFF_STG + 256 * 5 * 4);
    __syncthreads();
#pragma unroll
    for (int j = 0; j < 5; j++) { md[tid * 5 + j] = td[j]; mi[tid * 5 + j] = ti[j]; }
    __syncthreads();
    if (tid < 32) {
        float e[5]; int m[5];
#pragma unroll
        for (int j = 0; j < 5; j++) { e[j] = 3.4e38f; m[j] = 0; }
        for (int g = 0; g < 8; g++) {
            const int src = (g * 32 + tid) * 5;
#pragma unroll
            for (int j = 0; j < 5; j++) ins5(md[src + j], mi[src + j], e, m);
        }
        const int ob = (tid * GBLK + blockIdx.x) * K;
#pragma unroll
        for (int j = 0; j < 5; j++) { g_cand_d[ob + j] = e[j]; g_cand_i[ob + j] = m[j]; }
    }

    // ---- last-block exact refine + output (148 CTAs co-resident: one wave) ----
    __threadfence();
    __syncthreads();
    __shared__ unsigned rank_s;
    if (tid == 0) rank_s = atomicAdd(&g_done, 1u);
    __syncthreads();
    if (rank_s != GBLK - 1) return;

    float* ed  = (float*)(sm + OFF_STG);           // [256][8]
    int*   ei  = (int*)(ed + 2048);                // [256][8]
    float* fd  = (float*)(ei + 2048);              // [32][8]
    int*   fi  = (int*)(fd + 256);                 // [32][8]
    float* fsq = (float*)(fi + 256);               // [32][8]

    // phase 1: 8 threads/batch, strided scan of 740 approx candidates -> top-8 each
    {
        const int b = tid >> 3, s = tid & 7;
        float e8[8]; int m8[8];
#pragma unroll
        for (int j = 0; j < 8; j++) { e8[j] = 3.4e38f; m8[j] = 0; }
        const float* cd = g_cand_d + (size_t)b * GBLK * K;
        const int*   ci = g_cand_i + (size_t)b * GBLK * K;
        for (int c2 = s; c2 < GBLK * K; c2 += 8) ins8(cd[c2], ci[c2], e8, m8);
#pragma unroll
        for (int j = 0; j < 8; j++) { ed[tid * 8 + j] = e8[j]; ei[tid * 8 + j] = m8[j]; }
    }
    __syncthreads();

    // phase 2: one thread per batch merges 64 -> approx top-8
    if (tid < 32) {
        float e8[8]; int m8[8];
#pragma unroll
        for (int j = 0; j < 8; j++) { e8[j] = 3.4e38f; m8[j] = 0; }
        for (int s = 0; s < 8; s++) {
            const int src = (tid * 8 + s) * 8;
#pragma unroll
            for (int j = 0; j < 8; j++) ins8(ed[src + j], ei[src + j], e8, m8);
        }
#pragma unroll
        for (int j = 0; j < 8; j++) { fd[tid * 8 + j] = e8[j]; fi[tid * 8 + j] = m8[j]; }
    }
    __syncthreads();

    // phase 3: exact fp32 sq for each of the 8 candidates per batch
    {
        const int b = tid >> 3, s = tid & 7;
        const int idx = fi[b * 8 + s];
        const float4* rp = (const float4*)reps + (size_t)idx * 32;
        const float4* bp = (const float4*)g_brep + b * 32;
        float dot = 0.f, rn = 0.f;
#pragma unroll 8
        for (int k4 = 0; k4 < 32; k4++) {
            const float4 r = __ldg(rp + k4);
            const float4 a = bp[k4];
            dot = fmaf(a.x, r.x, dot); dot = fmaf(a.y, r.y, dot);
            dot = fmaf(a.z, r.z, dot); dot = fmaf(a.w, r.w, dot);
            rn  = fmaf(r.x, r.x, rn);  rn  = fmaf(r.y, r.y, rn);
            rn  = fmaf(r.z, r.z, rn);  rn  = fmaf(r.w, r.w, rn);
        }
        fsq[b * 8 + s] = an_s[b] + rn - 2.f * dot;
    }
    __syncthreads();

    // phase 4: exact top-5 of 8, sqrt, softmax, action gather
    if (tid < 32) {
        const int b = tid;
        float e[5]; int m[5];
#pragma unroll
        for (int j = 0; j < 5; j++) { e[j] = 3.4e38f; m[j] = 0; }
#pragma unroll
        for (int j = 0; j < 8; j++) ins5(fsq[b * 8 + j], fi[b * 8 + j], e, m);
        const float t0 = sqrtf(fmaxf(e[0], 1e-12f));
        const float t1 = sqrtf(fmaxf(e[1], 1e-12f));
        const float t2 = sqrtf(fmaxf(e[2], 1e-12f));
        const float t3 = sqrtf(fmaxf(e[3], 1e-12f));
        const float t4v = sqrtf(fmaxf(e[4], 1e-12f));
        const float dmin = t0;
        const float w0 = expf(dmin - t0);
        const float w1 = expf(dmin - t1);
        const float w2 = expf(dmin - t2);
        const float w3 = expf(dmin - t3);
        const float w4 = expf(dmin - t4v);
        const float inv = 1.f / (w0 + w1 + w2 + w3 + w4);
        const float* a0 = actions + (size_t)m[0] * A;
        const float* a1 = actions + (size_t)m[1] * A;
        const float* a2 = actions + (size_t)m[2] * A;
        const float* a3 = actions + (size_t)m[3] * A;
        const float* a4 = actions + (size_t)m[4] * A;
#pragma unroll
        for (int a = 0; a < A; a++)
            out[b * A + a] = (w0 * a0[a] + w1 * a1[a] + w2 * a2[a] +
                              w3 * a3[a] + w4 * a4[a]) * inv;
    }
    if (tid == 0) g_done = 0;
}

// ---------------- launch ----------------
extern "C" void kernel_launch(void* const* d_in, const int* in_sizes, int n_in,
                              void* d_out, int out_size)
{
    const float* x       = (const float*)d_in[0];
    const float* W       = (const float*)d_in[1];
    const float* b_enc   = (const float*)d_in[2];
    const float* reps    = (const float*)d_in[3];
    const float* actions = (const float*)d_in[4];
    const int N = in_sizes[3] / D;

    static int attr_done = 0;
    if (!attr_done) {
        cudaFuncSetAttribute(dist_topk_kernel,
                             cudaFuncAttributeMaxDynamicSharedMemorySize, SMEM_TOTAL);
        attr_done = 1;
    }

    enc_partial_kernel<<<dim3(KSPLIT, B / BT), 128>>>(x, W);
    enc_reduce_kernel<<<B, 128>>>(b_enc);
    dist_topk_kernel<<<GBLK, 256, SMEM_TOTAL>>>(reps, N, actions, (float*)d_out);
}